// round 10
// baseline (speedup 1.0000x reference)
#include <cuda_runtime.h>
#include <cstdint>
#include <cstdlib>

#define T_DIM 512
#define NC 65
#define NTT 64
#define KV 128
#define SS 192
#define D_DIM 256

#define LOG2E_F 1.4426950408889634f
#define LN2_F   0.6931471805599453f
#define KD_F (LOG2E_F / 128.0f)        // dyn: ct = n/128 -> log2 domain
#define KS_F (LOG2E_F * 0.15625f)      // sta: logit = n*20/128
#define FBIAS 8388624.0f               // 2^23 + 16

__device__ __forceinline__ float ex2f(float x) {
    float y; asm("ex2.approx.ftz.f32 %0, %1;" : "=f"(y) : "f"(x)); return y;
}

// df with sign flipped by bit31 of X (single LOP3, lut 0x78)
__device__ __forceinline__ float sxor(float df, uint32_t X) {
    uint32_t r;
    asm("lop3.b32 %0, %1, %2, 0x80000000, 0x78;"
        : "=r"(r) : "r"(__float_as_uint(df)), "r"(X));
    return __uint_as_float(r);
}

// float(clz(y)) - 16 without I2F: uint_as_float(clz|0x4B000000) = 2^23+clz
__device__ __forceinline__ float dminus16(uint32_t y) {
    uint32_t c = (uint32_t)__clz(y) | 0x4B000000u;
    return __uint_as_float(c) - FBIAS;
}

__global__ __launch_bounds__(512, 4)
void cg_kernel(const int* __restrict__ cur_tar, const int* __restrict__ cnc_loc,
               const int* __restrict__ sta_loc, const int* __restrict__ ttn_loc,
               const int* __restrict__ voc_loc, const float* __restrict__ sta_emb,
               const float* __restrict__ ttn_emb, float* __restrict__ out)
{
    __shared__ float2 s_dyn[NTT * 8];   // .x = w bits (abs | sign<<31), .y = A*KD
    __shared__ float2 s_sta[KV * 8];    // .x = w bits, .y = A*KS
    __shared__ float2 s_pe2[NTT / 2];   // p_eu pairs
    __shared__ float  s_eu[NTT];
    __shared__ float  s_semb[D_DIM];
    __shared__ float  s_pa[8];
    __shared__ float  s_c1;

    const int tid = threadIdx.x;
    const int t   = blockIdx.x;

    // ---------------- Phase A: pos words + A*K tables ----------------
    if (tid < SS) {
        const int s = tid;
        const int* sl   = sta_loc + (size_t)t * 8;
        const int* prow = (s < NTT) ? (ttn_loc + ((size_t)t * NTT + s) * 8)
                                    : (voc_loc + ((size_t)t * KV + (s - NTT)) * 8);
        int nsp[8];
        uint32_t wbits[8];
        int sumn = 0;
        #pragma unroll
        for (int p = 0; p < 8; p++) {
            int v  = prow[p];
            int sv = sl[p];
            uint32_t av = (uint32_t)abs(v);
            uint32_t as = (uint32_t)abs(sv);
            uint32_t x  = av ^ as;                 // <= 0xFFFF
            int d   = __clz(x + 1u) - 16;          // in [-1,15]
            int n   = ((v < 0) != (sv < 0)) ? -d : d;
            nsp[p] = n; sumn += n;
            wbits[p] = av | ((v < 0) ? 0x80000000u : 0u);
        }
        #pragma unroll
        for (int p = 0; p < 8; p++) {
            float An = (float)(sumn - nsp[p]);
            float2 e;
            e.x = __uint_as_float(wbits[p]);
            if (s < NTT) { e.y = An * KD_F; s_dyn[s * 8 + p] = e; }
            else         { e.y = An * KS_F; s_sta[(s - NTT) * 8 + p] = e; }
        }
    }
    if (tid < D_DIM) s_semb[tid] = sta_emb[(size_t)t * D_DIM + tid];
    __syncthreads();

    // ---------------- Phase B: eu logits (16 warps, 4 rounds) ----------------
    {
        const int wid = tid >> 5, lane = tid & 31;
        const float4* sb = (const float4*)s_semb;
        float4 b0 = sb[lane], b1 = sb[lane + 32];
        #pragma unroll
        for (int s = wid; s < NTT; s += 16) {
            const float4* ep = (const float4*)(ttn_emb + ((size_t)t * NTT + s) * D_DIM);
            float4 a0 = ep[lane], a1 = ep[lane + 32];
            float d = a0.x * b0.x + a0.y * b0.y + a0.z * b0.z + a0.w * b0.w
                    + a1.x * b1.x + a1.y * b1.y + a1.z * b1.z + a1.w * b1.w;
            #pragma unroll
            for (int off = 16; off; off >>= 1) d += __shfl_xor_sync(0xffffffffu, d, off);
            if (lane == 0) s_eu[s] = d;
        }
    }
    __syncthreads();

    // ---------------- Phase C: eu softmax (warp 0) ----------------
    if (tid < 32) {
        float e0 = s_eu[tid], e1 = s_eu[tid + 32];
        float mx = fmaxf(e0, e1);
        #pragma unroll
        for (int off = 16; off; off >>= 1) mx = fmaxf(mx, __shfl_xor_sync(0xffffffffu, mx, off));
        float z0 = e0 - mx, z1 = e1 - mx;
        float p0 = ex2f(z0 * LOG2E_F), p1 = ex2f(z1 * LOG2E_F);
        float Z = p0 + p1, W = p0 * z0 + p1 * z1;
        #pragma unroll
        for (int off = 16; off; off >>= 1) {
            Z += __shfl_xor_sync(0xffffffffu, Z, off);
            W += __shfl_xor_sync(0xffffffffu, W, off);
        }
        float rZ = 1.0f / Z;
        ((float*)s_pe2)[tid]      = p0 * rZ;
        ((float*)s_pe2)[tid + 32] = p1 * rZ;
        if (tid == 0) s_c1 = W * rZ - __logf(Z);
    }
    __syncthreads();

    // ------- Phase D: PA[p] (8 warps, warp=p) -------
    if (tid < 256) {
        const int p = tid >> 5, l = tid & 31;
        const float* pe = (const float*)s_pe2;
        float a = fmaf(pe[l],      s_dyn[l * 8 + p].y,        0.f);
        a       = fmaf(pe[l + 32], s_dyn[(l + 32) * 8 + p].y, a);
        #pragma unroll
        for (int off = 16; off; off >>= 1) a += __shfl_xor_sync(0xffffffffu, a, off);
        if (l == 0) s_pa[p] = a * LN2_F;
    }
    __syncthreads();

    // ---------------- Phase E: one candidate per thread ----------------
    const int tar = cur_tar[t];

    #pragma unroll 1
    for (int pass = 0; pass < 2; pass++) {
        int c, p;
        if (pass == 0) { c = tid >> 3; p = tid & 7; }
        else {
            if (tid < 504) break;          // only lanes 24-31 of last warp
            c = 64; p = tid - 504;
        }

        const int cv = cnc_loc[((size_t)t * NC + c) * 8 + p];
        const uint32_t wc = (uint32_t)abs(cv) | ((cv < 0) ? 0x80000000u : 0u);

        // dyn: s in [0,64)
        float se0 = 0.f, se1 = 0.f, acc0 = 0.f, acc1 = 0.f;
        const float2* dt = s_dyn + p;
        #pragma unroll 2
        for (int s = 0; s < NTT; s += 2) {
            float2 e0 = dt[(s + 0) * 8];
            float2 e1 = dt[(s + 1) * 8];
            float2 pp = s_pe2[s >> 1];
            {
                uint32_t X = __float_as_uint(e0.x) ^ wc;
                float dfs = sxor(dminus16((X & 0xFFFFu) + 1u), X);
                se0 += ex2f(fmaf(dfs, KD_F, e0.y));
                acc0 = fmaf(dfs, pp.x, acc0);
            }
            {
                uint32_t X = __float_as_uint(e1.x) ^ wc;
                float dfs = sxor(dminus16((X & 0xFFFFu) + 1u), X);
                se1 += ex2f(fmaf(dfs, KD_F, e1.y));
                acc1 = fmaf(dfs, pp.y, acc1);
            }
        }
        float ldd = s_c1 - s_pa[p] - (acc0 + acc1) * 0.0078125f + __logf(se0 + se1);
        out[((size_t)t * NC + c) * 8 + p] = ldd;

        // sta: k in [0,128)
        float sf0 = 0.f, sf1 = 0.f;
        const float2* st = s_sta + p;
        #pragma unroll 2
        for (int k = 0; k < KV; k += 2) {
            float2 e0 = st[(k + 0) * 8];
            float2 e1 = st[(k + 1) * 8];
            {
                uint32_t X = __float_as_uint(e0.x) ^ wc;
                float dfs = sxor(dminus16((X & 0xFFFFu) + 1u), X);
                sf0 += ex2f(fmaf(dfs, KS_F, e0.y));
            }
            {
                uint32_t X = __float_as_uint(e1.x) ^ wc;
                float dfs = sxor(dminus16((X & 0xFFFFu) + 1u), X);
                sf1 += ex2f(fmaf(dfs, KS_F, e1.y));
            }
        }
        float argt;
        {
            float2 e = st[tar * 8];
            uint32_t X = __float_as_uint(e.x) ^ wc;
            float dfs = sxor(dminus16((X & 0xFFFFu) + 1u), X);
            argt = fmaf(dfs, KS_F, e.y);
        }
        float lds_v = __logf(sf0 + sf1) - LN2_F * argt;
        out[(size_t)T_DIM * NC * 8 + ((size_t)t * NC + c) * 8 + p] = lds_v;
    }
}

extern "C" void kernel_launch(void* const* d_in, const int* in_sizes, int n_in,
                              void* d_out, int out_size)
{
    const int*   cur_tar = (const int*)d_in[0];
    const int*   cnc_loc = (const int*)d_in[1];
    const int*   sta_loc = (const int*)d_in[2];
    const int*   ttn_loc = (const int*)d_in[3];
    const int*   voc_loc = (const int*)d_in[4];
    const float* sta_emb = (const float*)d_in[5];
    const float* ttn_emb = (const float*)d_in[6];
    // d_in[7] = voc_emb: unused by the math (eu_val[:, 64:] is discarded)
    float* out = (float*)d_out;

    cg_kernel<<<T_DIM, 512>>>(cur_tar, cnc_loc, sta_loc, ttn_loc, voc_loc,
                              sta_emb, ttn_emb, out);
}

// round 11
// speedup vs baseline: 1.1628x; 1.1628x over previous
#include <cuda_runtime.h>
#include <cstdint>
#include <cstdlib>

#define T_DIM 512
#define NC 65
#define NTT 64
#define KV 128
#define SS 192
#define D_DIM 256

#define LOG2E_F 1.4426950408889634f
#define LN2_F   0.6931471805599453f
#define KD_F (LOG2E_F / 128.0f)        // dyn: ct = n/128 -> log2 domain
#define KS_F (LOG2E_F * 0.15625f)      // sta: logit = n*20/128
#define FBIAS 8388624.0f               // 2^23 + 16

__device__ __forceinline__ float ex2f(float x) {
    float y; asm("ex2.approx.ftz.f32 %0, %1;" : "=f"(y) : "f"(x)); return y;
}

// df with sign flipped by bit31 of X (single LOP3, lut 0x78)
__device__ __forceinline__ float sxor(float df, uint32_t X) {
    uint32_t r;
    asm("lop3.b32 %0, %1, %2, 0x80000000, 0x78;"
        : "=r"(r) : "r"(__float_as_uint(df)), "r"(X));
    return __uint_as_float(r);
}

// float(clz(y)) - 16 without I2F
__device__ __forceinline__ float dminus16(uint32_t y) {
    uint32_t c = (uint32_t)__clz(y) | 0x4B000000u;
    return __uint_as_float(c) - FBIAS;
}

// Two-candidate dyn unit
#define DYN_UNIT2(EE, PEV, SEA, SEB) {                                 \
    uint32_t wb = __float_as_uint((EE).x);                             \
    uint32_t XA = wb ^ wcA;                                            \
    uint32_t XB = wb ^ wcB;                                            \
    float dsA = sxor(dminus16((XA & 0xFFFFu) + 1u), XA);               \
    float dsB = sxor(dminus16((XB & 0xFFFFu) + 1u), XB);               \
    SEA += ex2f(fmaf(dsA, KD_F, (EE).y));                              \
    SEB += ex2f(fmaf(dsB, KD_F, (EE).y));                              \
    accA = fmaf(dsA, (PEV), accA);                                     \
    accB = fmaf(dsB, (PEV), accB); }

#define STA_UNIT2(EE, SFA, SFB) {                                      \
    uint32_t wb = __float_as_uint((EE).x);                             \
    uint32_t XA = wb ^ wcA;                                            \
    uint32_t XB = wb ^ wcB;                                            \
    SFA += ex2f(fmaf(sxor(dminus16((XA & 0xFFFFu) + 1u), XA), KS_F, (EE).y)); \
    SFB += ex2f(fmaf(sxor(dminus16((XB & 0xFFFFu) + 1u), XB), KS_F, (EE).y)); }

__global__ __launch_bounds__(288, 4)
void cg_kernel(const int* __restrict__ cur_tar, const int* __restrict__ cnc_loc,
               const int* __restrict__ sta_loc, const int* __restrict__ ttn_loc,
               const int* __restrict__ voc_loc, const float* __restrict__ sta_emb,
               const float* __restrict__ ttn_emb, float* __restrict__ out)
{
    __shared__ float2 s_dyn[NTT * 8];   // .x = w bits (abs | sign<<31), .y = A*KD
    __shared__ float2 s_sta[KV * 8];    // .x = w bits, .y = A*KS
    __shared__ float2 s_pe2[NTT / 2];   // p_eu pairs
    __shared__ float  s_eu[NTT];
    __shared__ float  s_semb[D_DIM];
    __shared__ float  s_pa[8];
    __shared__ float  s_c1;

    const int tid = threadIdx.x;
    const int t   = blockIdx.x;

    // ---------------- Phase A: pos words + A*K tables ----------------
    if (tid < SS) {
        const int s = tid;
        const int* sl   = sta_loc + (size_t)t * 8;
        const int* prow = (s < NTT) ? (ttn_loc + ((size_t)t * NTT + s) * 8)
                                    : (voc_loc + ((size_t)t * KV + (s - NTT)) * 8);
        int nsp[8];
        uint32_t wbits[8];
        int sumn = 0;
        #pragma unroll
        for (int p = 0; p < 8; p++) {
            int v  = prow[p];
            int sv = sl[p];
            uint32_t av = (uint32_t)abs(v);
            uint32_t as = (uint32_t)abs(sv);
            uint32_t x  = av ^ as;                 // <= 0xFFFF
            int d   = __clz(x + 1u) - 16;          // in [-1,15]
            int n   = ((v < 0) != (sv < 0)) ? -d : d;
            nsp[p] = n; sumn += n;
            wbits[p] = av | ((v < 0) ? 0x80000000u : 0u);
        }
        #pragma unroll
        for (int p = 0; p < 8; p++) {
            float An = (float)(sumn - nsp[p]);
            float2 e;
            e.x = __uint_as_float(wbits[p]);
            if (s < NTT) { e.y = An * KD_F; s_dyn[s * 8 + p] = e; }
            else         { e.y = An * KS_F; s_sta[(s - NTT) * 8 + p] = e; }
        }
    }
    for (int i = tid; i < D_DIM; i += 288) s_semb[i] = sta_emb[(size_t)t * D_DIM + i];
    __syncthreads();

    // ---------------- Phase B: eu logits (dot products) ----------------
    {
        const int wid = tid >> 5, lane = tid & 31;
        const float4* sb = (const float4*)s_semb;
        float4 b0 = sb[lane], b1 = sb[lane + 32];
        for (int s = wid; s < NTT; s += 9) {
            const float4* ep = (const float4*)(ttn_emb + ((size_t)t * NTT + s) * D_DIM);
            float4 a0 = ep[lane], a1 = ep[lane + 32];
            float d = a0.x * b0.x + a0.y * b0.y + a0.z * b0.z + a0.w * b0.w
                    + a1.x * b1.x + a1.y * b1.y + a1.z * b1.z + a1.w * b1.w;
            #pragma unroll
            for (int off = 16; off; off >>= 1) d += __shfl_xor_sync(0xffffffffu, d, off);
            if (lane == 0) s_eu[s] = d;
        }
    }
    __syncthreads();

    // ---------------- Phase C: eu softmax (warp 0) ----------------
    if (tid < 32) {
        float e0 = s_eu[tid], e1 = s_eu[tid + 32];
        float mx = fmaxf(e0, e1);
        #pragma unroll
        for (int off = 16; off; off >>= 1) mx = fmaxf(mx, __shfl_xor_sync(0xffffffffu, mx, off));
        float z0 = e0 - mx, z1 = e1 - mx;
        float p0 = ex2f(z0 * LOG2E_F), p1 = ex2f(z1 * LOG2E_F);
        float Z = p0 + p1, W = p0 * z0 + p1 * z1;
        #pragma unroll
        for (int off = 16; off; off >>= 1) {
            Z += __shfl_xor_sync(0xffffffffu, Z, off);
            W += __shfl_xor_sync(0xffffffffu, W, off);
        }
        float rZ = 1.0f / Z;
        ((float*)s_pe2)[tid]      = p0 * rZ;
        ((float*)s_pe2)[tid + 32] = p1 * rZ;
        if (tid == 0) s_c1 = W * rZ - __logf(Z);   // C1 = sum p*lp
    }
    __syncthreads();

    // ------- Phase D: PA[p] (8 warps, warp=p) -------
    if (tid < 256) {
        const int p = tid >> 5, l = tid & 31;
        const float* pe = (const float*)s_pe2;
        float a = fmaf(pe[l],      s_dyn[l * 8 + p].y,        0.f);
        a       = fmaf(pe[l + 32], s_dyn[(l + 32) * 8 + p].y, a);
        #pragma unroll
        for (int off = 16; off; off >>= 1) a += __shfl_xor_sync(0xffffffffu, a, off);
        if (l == 0) s_pa[p] = a * LN2_F;
    }
    __syncthreads();

    // ---------------- Phase E: each thread handles cA and cB = cA+33 ----------------
    if (tid < 264) {
        const int cA = tid >> 3;
        const int p  = tid & 7;
        const bool has2 = (cA < 32);
        const int cB = has2 ? cA + 33 : cA;

        const int cva = cnc_loc[((size_t)t * NC + cA) * 8 + p];
        const int cvb = cnc_loc[((size_t)t * NC + cB) * 8 + p];
        const uint32_t wcA = (uint32_t)abs(cva) | ((cva < 0) ? 0x80000000u : 0u);
        const uint32_t wcB = (uint32_t)abs(cvb) | ((cvb < 0) ? 0x80000000u : 0u);

        // dyn: s in [0,64), unroll 4, 4 se chains per candidate
        float seA0 = 0.f, seA1 = 0.f, seA2 = 0.f, seA3 = 0.f;
        float seB0 = 0.f, seB1 = 0.f, seB2 = 0.f, seB3 = 0.f;
        float accA = 0.f, accB = 0.f;
        const float2* dt = s_dyn + p;
        #pragma unroll 2
        for (int s = 0; s < NTT; s += 4) {
            float2 e0 = dt[(s + 0) * 8];
            float2 e1 = dt[(s + 1) * 8];
            float2 e2 = dt[(s + 2) * 8];
            float2 e3 = dt[(s + 3) * 8];
            float2 pp = s_pe2[(s >> 1) + 0];
            float2 pq = s_pe2[(s >> 1) + 1];
            DYN_UNIT2(e0, pp.x, seA0, seB0);
            DYN_UNIT2(e1, pp.y, seA1, seB1);
            DYN_UNIT2(e2, pq.x, seA2, seB2);
            DYN_UNIT2(e3, pq.y, seA3, seB3);
        }
        float seA = (seA0 + seA1) + (seA2 + seA3);
        float seB = (seB0 + seB1) + (seB2 + seB3);
        float base = s_c1 - s_pa[p];
        float lddA = base - accA * 0.0078125f + __logf(seA);
        float lddB = base - accB * 0.0078125f + __logf(seB);
        out[((size_t)t * NC + cA) * 8 + p] = lddA;
        if (has2) out[((size_t)t * NC + cB) * 8 + p] = lddB;

        // sta: k in [0,128), unroll 4, 4 sf chains per candidate
        float sfA0 = 0.f, sfA1 = 0.f, sfA2 = 0.f, sfA3 = 0.f;
        float sfB0 = 0.f, sfB1 = 0.f, sfB2 = 0.f, sfB3 = 0.f;
        const float2* st = s_sta + p;
        #pragma unroll 2
        for (int k = 0; k < KV; k += 4) {
            float2 e0 = st[(k + 0) * 8];
            float2 e1 = st[(k + 1) * 8];
            float2 e2 = st[(k + 2) * 8];
            float2 e3 = st[(k + 3) * 8];
            STA_UNIT2(e0, sfA0, sfB0);
            STA_UNIT2(e1, sfA1, sfB1);
            STA_UNIT2(e2, sfA2, sfB2);
            STA_UNIT2(e3, sfA3, sfB3);
        }
        const int tar = cur_tar[t];
        float argA, argB;
        {
            float2 e = st[tar * 8];
            uint32_t wb = __float_as_uint(e.x);
            uint32_t XA = wb ^ wcA;
            uint32_t XB = wb ^ wcB;
            argA = fmaf(sxor(dminus16((XA & 0xFFFFu) + 1u), XA), KS_F, e.y);
            argB = fmaf(sxor(dminus16((XB & 0xFFFFu) + 1u), XB), KS_F, e.y);
        }
        float ldsA = __logf((sfA0 + sfA1) + (sfA2 + sfA3)) - LN2_F * argA;
        float ldsB = __logf((sfB0 + sfB1) + (sfB2 + sfB3)) - LN2_F * argB;
        float* outS = out + (size_t)T_DIM * NC * 8;
        outS[((size_t)t * NC + cA) * 8 + p] = ldsA;
        if (has2) outS[((size_t)t * NC + cB) * 8 + p] = ldsB;
    }
}

extern "C" void kernel_launch(void* const* d_in, const int* in_sizes, int n_in,
                              void* d_out, int out_size)
{
    const int*   cur_tar = (const int*)d_in[0];
    const int*   cnc_loc = (const int*)d_in[1];
    const int*   sta_loc = (const int*)d_in[2];
    const int*   ttn_loc = (const int*)d_in[3];
    const int*   voc_loc = (const int*)d_in[4];
    const float* sta_emb = (const float*)d_in[5];
    const float* ttn_emb = (const float*)d_in[6];
    // d_in[7] = voc_emb: unused by the math (eu_val[:, 64:] is discarded)
    float* out = (float*)d_out;

    cg_kernel<<<T_DIM, 288>>>(cur_tar, cnc_loc, sta_loc, ttn_loc, voc_loc,
                              sta_emb, ttn_emb, out);
}